// round 5
// baseline (speedup 1.0000x reference)
#include <cuda_runtime.h>
#include <math.h>

#define N_NODES 50000
#define N_EDGES 800000
#define NFEAT   256
#define NHID    64
#define NCLASS  40
#define LOGSM_OFF (N_NODES * NCLASS)

typedef unsigned long long ull;

// Scratch (static __device__ — no allocations allowed)
__device__ float g_A[N_NODES * NHID];      // x @ W1
__device__ float g_hacc[N_NODES * NHID];   // spmm1 accumulator
__device__ float g_B[N_NODES * NCLASS];    // relu(hacc+b1) @ W2
__device__ float g_lacc[N_NODES * NCLASS]; // spmm2 accumulator

// ---------------------------------------------------------------------------
// f32x2 packed-FMA helpers
// ---------------------------------------------------------------------------
__device__ __forceinline__ void ffma2(ull& acc, ull ab, ull w) {
    asm("fma.rn.f32x2 %0, %1, %2, %0;" : "+l"(acc) : "l"(ab), "l"(w));
}
__device__ __forceinline__ ull pack2(float v) {
    ull r;
    asm("mov.b64 %0, {%1, %1};" : "=l"(r) : "r"(__float_as_uint(v)));
    return r;
}
union F4U2 { float4 f4; ull u2[2]; };
union F2U1 { float2 f2; ull u; };

// ---------------------------------------------------------------------------
// GEMM1 + accumulator zeroing.
// Block = 256 threads = 32 node-pairs x 8 col-groups. 64 nodes/block.
// Each thread: 2 nodes x 8 cols over K=256. W1 smem-staged in 2 phases.
// Also zeroes g_hacc and g_lacc (stride loop, hidden under compute).
// ---------------------------------------------------------------------------
__global__ __launch_bounds__(256) void gemm1_kernel(const float* __restrict__ x,
                                                    const float* __restrict__ W1) {
    __shared__ float W1s[128 * NHID]; // 32 KB

    // ---- fused zeroing of both accumulators ----
    {
        int idx = blockIdx.x * 256 + threadIdx.x;
        int nthr = gridDim.x * 256;
        float4 z = make_float4(0.f, 0.f, 0.f, 0.f);
        float4* h4 = (float4*)g_hacc;
        float4* l4 = (float4*)g_lacc;
        for (int i = idx; i < (N_NODES * NHID) / 4; i += nthr) h4[i] = z;
        for (int i = idx; i < (N_NODES * NCLASS) / 4; i += nthr) l4[i] = z;
    }

    int pair = blockIdx.x * 32 + (threadIdx.x >> 3); // node pair index
    int g = threadIdx.x & 7;                          // col group: cols [g*8, g*8+8)
    bool valid = (pair < N_NODES / 2);
    int n0 = valid ? pair * 2 : 0;
    int n1 = n0 + 1;

    ull acc0[4], acc1[4];
#pragma unroll
    for (int j = 0; j < 4; j++) { acc0[j] = 0ull; acc1[j] = 0ull; }

    const float4* xv = (const float4*)x;

    for (int ph = 0; ph < 2; ph++) {
        __syncthreads();
        {
            const float4* Wg = (const float4*)(W1 + ph * 128 * NHID);
            float4* Ws = (float4*)W1s;
            for (int i = threadIdx.x; i < (128 * NHID) / 4; i += 256)
                Ws[i] = Wg[i];
        }
        __syncthreads();

        int kbase = ph * 128;
#pragma unroll 4
        for (int k4 = 0; k4 < 32; k4++) {
            float4 xa = xv[n0 * (NFEAT / 4) + (kbase >> 2) + k4];
            float4 xb = xv[n1 * (NFEAT / 4) + (kbase >> 2) + k4];
            float xs0[4] = {xa.x, xa.y, xa.z, xa.w};
            float xs1[4] = {xb.x, xb.y, xb.z, xb.w};
#pragma unroll
            for (int u = 0; u < 4; u++) {
                ull va = pack2(xs0[u]);
                ull vb = pack2(xs1[u]);
                const float4* wrow = (const float4*)(W1s + (k4 * 4 + u) * NHID + g * 8);
                F4U2 w0; w0.f4 = wrow[0];
                F4U2 w1; w1.f4 = wrow[1];
                ffma2(acc0[0], va, w0.u2[0]); ffma2(acc0[1], va, w0.u2[1]);
                ffma2(acc0[2], va, w1.u2[0]); ffma2(acc0[3], va, w1.u2[1]);
                ffma2(acc1[0], vb, w0.u2[0]); ffma2(acc1[1], vb, w0.u2[1]);
                ffma2(acc1[2], vb, w1.u2[0]); ffma2(acc1[3], vb, w1.u2[1]);
            }
        }
    }

    if (valid) {
        float4* out = (float4*)g_A;
        F4U2 o;
        o.u2[0] = acc0[0]; o.u2[1] = acc0[1]; out[n0 * 16 + g * 2]     = o.f4;
        o.u2[0] = acc0[2]; o.u2[1] = acc0[3]; out[n0 * 16 + g * 2 + 1] = o.f4;
        o.u2[0] = acc1[0]; o.u2[1] = acc1[1]; out[n1 * 16 + g * 2]     = o.f4;
        o.u2[0] = acc1[2]; o.u2[1] = acc1[3]; out[n1 * 16 + g * 2 + 1] = o.f4;
    }
}

// ---------------------------------------------------------------------------
// SpMM1: g_hacc[dst] += g_A[src] * w   (16 threads/edge, ONE float4 RED each)
// ---------------------------------------------------------------------------
__global__ void spmm1_kernel(const float* __restrict__ ew,
                             const int* __restrict__ esrc,
                             const int* __restrict__ edst) {
    int gid = blockIdx.x * blockDim.x + threadIdx.x;
    int e = gid >> 4;
    if (e >= N_EDGES) return;
    int q = gid & 15;

    int s = __ldg(&esrc[e]);
    int d = __ldg(&edst[e]);
    float w = __ldg(&ew[e]);

    float4 a = ((const float4*)g_A)[s * 16 + q];
    float4 m = make_float4(a.x * w, a.y * w, a.z * w, a.w * w);
    atomicAdd((float4*)&g_hacc[d * NHID + q * 4], m);
}

// ---------------------------------------------------------------------------
// Layer2: h = relu(g_hacc + b1); g_B = h @ W2
// 4 threads/node, 10 cols each (float2 LDS for alignment).
// ---------------------------------------------------------------------------
__global__ __launch_bounds__(256) void layer2_kernel(const float* __restrict__ b1,
                                                     const float* __restrict__ W2) {
    __shared__ float W2s[NHID * NCLASS]; // 10 KB
    __shared__ float b1s[NHID];

    for (int i = threadIdx.x; i < NHID * NCLASS; i += 256) W2s[i] = W2[i];
    if (threadIdx.x < NHID) b1s[threadIdx.x] = b1[threadIdx.x];
    __syncthreads();

    int tid = blockIdx.x * 256 + threadIdx.x;
    int node = tid >> 2;
    int q = tid & 3;             // cols [q*10, q*10+10)
    if (node >= N_NODES) return;
    int cbase = q * 10;

    ull acc[5];
#pragma unroll
    for (int j = 0; j < 5; j++) acc[j] = 0ull;

    const float4* hin = (const float4*)(g_hacc + node * NHID);
#pragma unroll 4
    for (int k4 = 0; k4 < 16; k4++) {
        float4 hv = hin[k4];
        float hs[4] = {hv.x, hv.y, hv.z, hv.w};
#pragma unroll
        for (int u = 0; u < 4; u++) {
            int k = k4 * 4 + u;
            float h = fmaxf(hs[u] + b1s[k], 0.f);
            ull hh = pack2(h);
            const float2* wrow = (const float2*)(W2s + k * NCLASS + cbase);
#pragma unroll
            for (int jj = 0; jj < 5; jj++) {
                F2U1 w; w.f2 = wrow[jj];
                ffma2(acc[jj], hh, w.u);
            }
        }
    }

    float2* out = (float2*)(g_B + node * NCLASS + cbase);
#pragma unroll
    for (int jj = 0; jj < 5; jj++) {
        F2U1 o; o.u = acc[jj];
        out[jj] = o.f2;
    }
}

// ---------------------------------------------------------------------------
// SpMM2: g_lacc[dst] += g_B[src] * w   (10 threads/edge, ONE float4 RED each)
// ---------------------------------------------------------------------------
__global__ void spmm2_kernel(const float* __restrict__ ew,
                             const int* __restrict__ esrc,
                             const int* __restrict__ edst) {
    int gid = blockIdx.x * blockDim.x + threadIdx.x;
    int e = gid / 10;
    if (e >= N_EDGES) return;
    int q = gid - e * 10;

    int s = __ldg(&esrc[e]);
    int d = __ldg(&edst[e]);
    float w = __ldg(&ew[e]);

    float4 a = ((const float4*)g_B)[s * 10 + q];
    float4 m = make_float4(a.x * w, a.y * w, a.z * w, a.w * w);
    atomicAdd((float4*)&g_lacc[d * NCLASS + q * 4], m);
}

// ---------------------------------------------------------------------------
// Finalize: logits = g_lacc + b2; out[0:2M]=logits, out[2M:4M]=log_softmax
// ---------------------------------------------------------------------------
__global__ __launch_bounds__(256) void finalize_kernel(const float* __restrict__ b2,
                                                       float* __restrict__ out) {
    __shared__ float b2s[NCLASS];
    if (threadIdx.x < NCLASS) b2s[threadIdx.x] = b2[threadIdx.x];
    __syncthreads();

    int node = blockIdx.x * 256 + threadIdx.x;
    if (node >= N_NODES) return;

    float v[NCLASS];
    float mx = -INFINITY;
    const float4* lin = (const float4*)(g_lacc + node * NCLASS);
#pragma unroll
    for (int jj = 0; jj < 10; jj++) {
        float4 a = lin[jj];
        v[jj * 4 + 0] = a.x + b2s[jj * 4 + 0];
        v[jj * 4 + 1] = a.y + b2s[jj * 4 + 1];
        v[jj * 4 + 2] = a.z + b2s[jj * 4 + 2];
        v[jj * 4 + 3] = a.w + b2s[jj * 4 + 3];
    }
#pragma unroll
    for (int j = 0; j < NCLASS; j++) mx = fmaxf(mx, v[j]);
    float s = 0.f;
#pragma unroll
    for (int j = 0; j < NCLASS; j++) s += expf(v[j] - mx);
    float lse = mx + logf(s);

    float4* o1 = (float4*)(out + node * NCLASS);
    float4* o2 = (float4*)(out + LOGSM_OFF + node * NCLASS);
#pragma unroll
    for (int jj = 0; jj < 10; jj++) {
        float4 a = make_float4(v[jj * 4 + 0], v[jj * 4 + 1],
                               v[jj * 4 + 2], v[jj * 4 + 3]);
        o1[jj] = a;
        float4 b = make_float4(a.x - lse, a.y - lse, a.z - lse, a.w - lse);
        o2[jj] = b;
    }
}

// ---------------------------------------------------------------------------
extern "C" void kernel_launch(void* const* d_in, const int* in_sizes, int n_in,
                              void* d_out, int out_size) {
    const float* x   = (const float*)d_in[0];
    const float* W1  = (const float*)d_in[1];
    const float* b1  = (const float*)d_in[2];
    const float* W2  = (const float*)d_in[3];
    const float* b2  = (const float*)d_in[4];
    const float* ew  = (const float*)d_in[5];
    const int*  esrc = (const int*)d_in[6];
    const int*  edst = (const int*)d_in[7];
    float* out = (float*)d_out;

    // GEMM1 + fused accumulator zeroing (64 nodes per block)
    {
        int nblk = (N_NODES / 2 + 31) / 32; // 782
        gemm1_kernel<<<nblk, 256>>>(x, W1);
    }
    // SpMM1 (vector RED scatter)
    {
        int total = N_EDGES * 16; // 12.8M
        spmm1_kernel<<<(total + 255) / 256, 256>>>(ew, esrc, edst);
    }
    // ReLU + bias + GEMM2 (4 threads/node)
    {
        int total = N_NODES * 4;
        layer2_kernel<<<(total + 255) / 256, 256>>>(b1, W2);
    }
    // SpMM2 (vector RED scatter)
    {
        int total = N_EDGES * 10; // 8M
        spmm2_kernel<<<(total + 255) / 256, 256>>>(ew, esrc, edst);
    }
    // bias + log_softmax + write both outputs
    finalize_kernel<<<(N_NODES + 255) / 256, 256>>>(b2, out);
}

// round 6
// speedup vs baseline: 1.0242x; 1.0242x over previous
#include <cuda_runtime.h>
#include <math.h>

#define N_NODES 50000
#define N_EDGES 800000
#define NFEAT   256
#define NHID    64
#define NCLASS  40
#define LOGSM_OFF (N_NODES * NCLASS)
#define HALF_E  (N_EDGES / 2)

typedef unsigned long long ull;

// Scratch (static __device__ — no allocations allowed)
__device__ float g_A[N_NODES * NHID];      // x @ W1
__device__ float g_hacc[N_NODES * NHID];   // spmm1 accumulator
__device__ float g_B[N_NODES * NCLASS];    // relu(hacc+b1) @ W2
__device__ float g_lacc[N_NODES * NCLASS]; // spmm2 accumulator

// ---------------------------------------------------------------------------
// f32x2 packed-FMA helpers
// ---------------------------------------------------------------------------
__device__ __forceinline__ void ffma2(ull& acc, ull ab, ull w) {
    asm("fma.rn.f32x2 %0, %1, %2, %0;" : "+l"(acc) : "l"(ab), "l"(w));
}
__device__ __forceinline__ ull pack2(float v) {
    ull r;
    asm("mov.b64 %0, {%1, %1};" : "=l"(r) : "r"(__float_as_uint(v)));
    return r;
}
union F4U2 { float4 f4; ull u2[2]; };
union F2U1 { float2 f2; ull u; };

// ---------------------------------------------------------------------------
// Zero both accumulators
// ---------------------------------------------------------------------------
__global__ void zero_acc_kernel() {
    int i = blockIdx.x * blockDim.x + threadIdx.x;
    float4 z = make_float4(0.f, 0.f, 0.f, 0.f);
    if (i < (N_NODES * NHID) / 4)   ((float4*)g_hacc)[i] = z;
    if (i < (N_NODES * NCLASS) / 4) ((float4*)g_lacc)[i] = z;
}

// ---------------------------------------------------------------------------
// GEMM1: g_A = x @ W1.  256 thr/block = 128 nodes x 2 col-halves (32 cols).
// x traffic only 2x (vs 8x in the failed R5 layout). W1 smem, 2 phases.
// ---------------------------------------------------------------------------
__global__ __launch_bounds__(256) void gemm1_kernel(const float* __restrict__ x,
                                                    const float* __restrict__ W1) {
    __shared__ float W1s[128 * NHID]; // 32 KB

    int node = blockIdx.x * 128 + (threadIdx.x >> 1);
    int half = threadIdx.x & 1;          // cols [half*32, half*32+32)
    bool valid = (node < N_NODES);
    int n0 = valid ? node : 0;

    ull acc[16];
#pragma unroll
    for (int j = 0; j < 16; j++) acc[j] = 0ull;

    const float4* xv = (const float4*)x;

    for (int ph = 0; ph < 2; ph++) {
        __syncthreads();
        {
            const float4* Wg = (const float4*)(W1 + ph * 128 * NHID);
            float4* Ws = (float4*)W1s;
            for (int i = threadIdx.x; i < (128 * NHID) / 4; i += 256)
                Ws[i] = Wg[i];
        }
        __syncthreads();

        int kb4 = ph * 32;
#pragma unroll 4
        for (int k4 = 0; k4 < 32; k4++) {
            float4 xa = xv[n0 * (NFEAT / 4) + kb4 + k4];
            float xs[4] = {xa.x, xa.y, xa.z, xa.w};
#pragma unroll
            for (int u = 0; u < 4; u++) {
                ull vv = pack2(xs[u]);
                const float4* wrow =
                    (const float4*)(W1s + (k4 * 4 + u) * NHID + half * 32);
#pragma unroll
                for (int jj = 0; jj < 8; jj++) {
                    F4U2 w; w.f4 = wrow[jj];
                    ffma2(acc[2 * jj],     vv, w.u2[0]);
                    ffma2(acc[2 * jj + 1], vv, w.u2[1]);
                }
            }
        }
    }

    if (valid) {
        float4* out = (float4*)g_A;
#pragma unroll
        for (int jj = 0; jj < 8; jj++) {
            F4U2 o; o.u2[0] = acc[2 * jj]; o.u2[1] = acc[2 * jj + 1];
            out[n0 * 16 + half * 8 + jj] = o.f4;
        }
    }
}

// ---------------------------------------------------------------------------
// SpMM1: 16 threads per EDGE-PAIR (edges p and p+HALF_E) — 2 indep chains.
// ---------------------------------------------------------------------------
__global__ void spmm1_kernel(const float* __restrict__ ew,
                             const int* __restrict__ esrc,
                             const int* __restrict__ edst) {
    int gid = blockIdx.x * blockDim.x + threadIdx.x;
    int p = gid >> 4;
    if (p >= HALF_E) return;
    int q = gid & 15;
    int e0 = p, e1 = p + HALF_E;

    int   s0 = __ldg(&esrc[e0]), s1 = __ldg(&esrc[e1]);
    int   d0 = __ldg(&edst[e0]), d1 = __ldg(&edst[e1]);
    float w0 = __ldg(&ew[e0]),   w1 = __ldg(&ew[e1]);

    const float4* A = (const float4*)g_A;
    float4 a0 = A[s0 * 16 + q];
    float4 a1 = A[s1 * 16 + q];
    float4 m0 = make_float4(a0.x * w0, a0.y * w0, a0.z * w0, a0.w * w0);
    float4 m1 = make_float4(a1.x * w1, a1.y * w1, a1.z * w1, a1.w * w1);
    atomicAdd((float4*)&g_hacc[d0 * NHID + q * 4], m0);
    atomicAdd((float4*)&g_hacc[d1 * NHID + q * 4], m1);
}

// ---------------------------------------------------------------------------
// Layer2: h = relu(g_hacc + b1); g_B = h @ W2.  4 threads/node, 10 cols each.
// ---------------------------------------------------------------------------
__global__ __launch_bounds__(256) void layer2_kernel(const float* __restrict__ b1,
                                                     const float* __restrict__ W2) {
    __shared__ float W2s[NHID * NCLASS]; // 10 KB
    __shared__ float b1s[NHID];

    for (int i = threadIdx.x; i < NHID * NCLASS; i += 256) W2s[i] = W2[i];
    if (threadIdx.x < NHID) b1s[threadIdx.x] = b1[threadIdx.x];
    __syncthreads();

    int tid = blockIdx.x * 256 + threadIdx.x;
    int node = tid >> 2;
    int q = tid & 3;             // cols [q*10, q*10+10)
    if (node >= N_NODES) return;
    int cbase = q * 10;

    ull acc[5];
#pragma unroll
    for (int j = 0; j < 5; j++) acc[j] = 0ull;

    const float4* hin = (const float4*)(g_hacc + node * NHID);
#pragma unroll 4
    for (int k4 = 0; k4 < 16; k4++) {
        float4 hv = hin[k4];
        float hs[4] = {hv.x, hv.y, hv.z, hv.w};
#pragma unroll
        for (int u = 0; u < 4; u++) {
            int k = k4 * 4 + u;
            float h = fmaxf(hs[u] + b1s[k], 0.f);
            ull hh = pack2(h);
            const float2* wrow = (const float2*)(W2s + k * NCLASS + cbase);
#pragma unroll
            for (int jj = 0; jj < 5; jj++) {
                F2U1 w; w.f2 = wrow[jj];
                ffma2(acc[jj], hh, w.u);
            }
        }
    }

    float2* out = (float2*)(g_B + node * NCLASS + cbase);
#pragma unroll
    for (int jj = 0; jj < 5; jj++) {
        F2U1 o; o.u = acc[jj];
        out[jj] = o.f2;
    }
}

// ---------------------------------------------------------------------------
// SpMM2: 10 threads per EDGE-PAIR — 2 independent chains.
// ---------------------------------------------------------------------------
__global__ void spmm2_kernel(const float* __restrict__ ew,
                             const int* __restrict__ esrc,
                             const int* __restrict__ edst) {
    int gid = blockIdx.x * blockDim.x + threadIdx.x;
    int p = gid / 10;
    if (p >= HALF_E) return;
    int q = gid - p * 10;
    int e0 = p, e1 = p + HALF_E;

    int   s0 = __ldg(&esrc[e0]), s1 = __ldg(&esrc[e1]);
    int   d0 = __ldg(&edst[e0]), d1 = __ldg(&edst[e1]);
    float w0 = __ldg(&ew[e0]),   w1 = __ldg(&ew[e1]);

    const float4* B = (const float4*)g_B;
    float4 a0 = B[s0 * 10 + q];
    float4 a1 = B[s1 * 10 + q];
    float4 m0 = make_float4(a0.x * w0, a0.y * w0, a0.z * w0, a0.w * w0);
    float4 m1 = make_float4(a1.x * w1, a1.y * w1, a1.z * w1, a1.w * w1);
    atomicAdd((float4*)&g_lacc[d0 * NCLASS + q * 4], m0);
    atomicAdd((float4*)&g_lacc[d1 * NCLASS + q * 4], m1);
}

// ---------------------------------------------------------------------------
// Finalize: logits = g_lacc + b2; out[0:2M]=logits, out[2M:4M]=log_softmax
// ---------------------------------------------------------------------------
__global__ __launch_bounds__(256) void finalize_kernel(const float* __restrict__ b2,
                                                       float* __restrict__ out) {
    __shared__ float b2s[NCLASS];
    if (threadIdx.x < NCLASS) b2s[threadIdx.x] = b2[threadIdx.x];
    __syncthreads();

    int node = blockIdx.x * 256 + threadIdx.x;
    if (node >= N_NODES) return;

    float v[NCLASS];
    float mx = -INFINITY;
    const float4* lin = (const float4*)(g_lacc + node * NCLASS);
#pragma unroll
    for (int jj = 0; jj < 10; jj++) {
        float4 a = lin[jj];
        v[jj * 4 + 0] = a.x + b2s[jj * 4 + 0];
        v[jj * 4 + 1] = a.y + b2s[jj * 4 + 1];
        v[jj * 4 + 2] = a.z + b2s[jj * 4 + 2];
        v[jj * 4 + 3] = a.w + b2s[jj * 4 + 3];
    }
#pragma unroll
    for (int j = 0; j < NCLASS; j++) mx = fmaxf(mx, v[j]);
    float s = 0.f;
#pragma unroll
    for (int j = 0; j < NCLASS; j++) s += expf(v[j] - mx);
    float lse = mx + logf(s);

    float4* o1 = (float4*)(out + node * NCLASS);
    float4* o2 = (float4*)(out + LOGSM_OFF + node * NCLASS);
#pragma unroll
    for (int jj = 0; jj < 10; jj++) {
        float4 a = make_float4(v[jj * 4 + 0], v[jj * 4 + 1],
                               v[jj * 4 + 2], v[jj * 4 + 3]);
        o1[jj] = a;
        float4 b = make_float4(a.x - lse, a.y - lse, a.z - lse, a.w - lse);
        o2[jj] = b;
    }
}

// ---------------------------------------------------------------------------
extern "C" void kernel_launch(void* const* d_in, const int* in_sizes, int n_in,
                              void* d_out, int out_size) {
    const float* x   = (const float*)d_in[0];
    const float* W1  = (const float*)d_in[1];
    const float* b1  = (const float*)d_in[2];
    const float* W2  = (const float*)d_in[3];
    const float* b2  = (const float*)d_in[4];
    const float* ew  = (const float*)d_in[5];
    const int*  esrc = (const int*)d_in[6];
    const int*  edst = (const int*)d_in[7];
    float* out = (float*)d_out;

    // Zero accumulators
    {
        int n4 = (N_NODES * NHID) / 4;
        zero_acc_kernel<<<(n4 + 255) / 256, 256>>>();
    }
    // GEMM1 (2 col-halves per node)
    gemm1_kernel<<<(N_NODES + 127) / 128, 256>>>(x, W1);
    // SpMM1 (edge-pair ILP, vector RED)
    {
        int total = HALF_E * 16; // 6.4M
        spmm1_kernel<<<(total + 255) / 256, 256>>>(ew, esrc, edst);
    }
    // ReLU + bias + GEMM2 (4 threads/node)
    {
        int total = N_NODES * 4;
        layer2_kernel<<<(total + 255) / 256, 256>>>(b1, W2);
    }
    // SpMM2 (edge-pair ILP, vector RED)
    {
        int total = HALF_E * 10; // 4M
        spmm2_kernel<<<(total + 255) / 256, 256>>>(ew, esrc, edst);
    }
    // bias + log_softmax + write both outputs
    finalize_kernel<<<(N_NODES + 255) / 256, 256>>>(b2, out);
}

// round 7
// speedup vs baseline: 1.1999x; 1.1716x over previous
#include <cuda_runtime.h>
#include <math.h>

#define N_NODES 50000
#define N_EDGES 800000
#define NFEAT   256
#define NHID    64
#define NCLASS  40
#define LOGSM_OFF (N_NODES * NCLASS)

typedef unsigned long long ull;

// Scratch (static __device__ — no allocations allowed)
__device__ float g_A[N_NODES * NHID];      // x @ W1
__device__ float g_hacc[N_NODES * NHID];   // spmm1 accumulator
__device__ float g_B[N_NODES * NCLASS];    // relu(hacc+b1) @ W2
__device__ float g_lacc[N_NODES * NCLASS]; // spmm2 accumulator

// ---------------------------------------------------------------------------
// f32x2 packed-FMA helpers
// ---------------------------------------------------------------------------
__device__ __forceinline__ void ffma2(ull& acc, ull ab, ull w) {
    asm("fma.rn.f32x2 %0, %1, %2, %0;" : "+l"(acc) : "l"(ab), "l"(w));
}
__device__ __forceinline__ ull pack2(float v) {
    ull r;
    asm("mov.b64 %0, {%1, %1};" : "=l"(r) : "r"(__float_as_uint(v)));
    return r;
}
union F4U2 { float4 f4; ull u2[2]; };

// ---------------------------------------------------------------------------
// Zero both accumulators
// ---------------------------------------------------------------------------
__global__ void zero_acc_kernel() {
    int i = blockIdx.x * blockDim.x + threadIdx.x;
    float4 z = make_float4(0.f, 0.f, 0.f, 0.f);
    if (i < (N_NODES * NHID) / 4)   ((float4*)g_hacc)[i] = z;
    if (i < (N_NODES * NCLASS) / 4) ((float4*)g_lacc)[i] = z;
}

// ---------------------------------------------------------------------------
// GEMM1: g_A = x @ W1, K-SPLIT x2.
// Block = 256 threads: threads [0,128) = K-half 0, [128,256) = K-half 1
// (warp-uniform kh => W1 LDS stays broadcast, no bank conflicts).
// Each thread: 1 node, all 64 cols, over its disjoint 128-element K half.
// Full W1 (64KB) in dynamic smem; combine halves through smem (buffer reused).
// 100K threads total (2x R4) with ZERO redundant global traffic.
// ---------------------------------------------------------------------------
__global__ __launch_bounds__(256) void gemm1_kernel(const float* __restrict__ x,
                                                    const float* __restrict__ W1) {
    extern __shared__ float4 smem4[];   // 64 KB: full W1 [256x64], then reused
    float* W1s = (float*)smem4;

    // Stage full W1
    {
        const float4* Wg = (const float4*)W1;
        for (int i = threadIdx.x; i < (NFEAT * NHID) / 4; i += 256)
            smem4[i] = Wg[i];
    }
    __syncthreads();

    int nl = threadIdx.x & 127;          // local node 0..127
    int kh = threadIdx.x >> 7;           // K half 0/1 (warp-uniform)
    int node = blockIdx.x * 128 + nl;
    bool valid = (node < N_NODES);
    int n0 = valid ? node : 0;

    ull acc[32];
#pragma unroll
    for (int j = 0; j < 32; j++) acc[j] = 0ull;

    const float4* xv = (const float4*)x;
    int xbase = n0 * (NFEAT / 4) + kh * 32;
    int wrow_base = kh * 128;

#pragma unroll 2
    for (int k4 = 0; k4 < 32; k4++) {
        float4 xa = xv[xbase + k4];
        float xs[4] = {xa.x, xa.y, xa.z, xa.w};
#pragma unroll
        for (int u = 0; u < 4; u++) {
            ull vv = pack2(xs[u]);
            const float4* wrow =
                (const float4*)(W1s + (wrow_base + k4 * 4 + u) * NHID);
#pragma unroll
            for (int jj = 0; jj < 16; jj++) {
                F4U2 w; w.f4 = wrow[jj];
                ffma2(acc[2 * jj],     vv, w.u2[0]);
                ffma2(acc[2 * jj + 1], vv, w.u2[1]);
            }
        }
    }

    // Combine the two K-halves through smem (reuse the W1 buffer).
    __syncthreads();  // everyone done reading W1
    if (kh == 1) {
#pragma unroll
        for (int jj = 0; jj < 16; jj++) {
            F4U2 o; o.u2[0] = acc[2 * jj]; o.u2[1] = acc[2 * jj + 1];
            smem4[nl * 16 + jj] = o.f4;   // 128 nodes x 64 floats = 32 KB
        }
    }
    __syncthreads();
    if (kh == 0 && valid) {
        float4* outp = (float4*)g_A;
#pragma unroll
        for (int jj = 0; jj < 16; jj++) {
            float4 p = smem4[nl * 16 + jj];
            F4U2 o; o.u2[0] = acc[2 * jj]; o.u2[1] = acc[2 * jj + 1];
            float4 r = make_float4(o.f4.x + p.x, o.f4.y + p.y,
                                   o.f4.z + p.z, o.f4.w + p.w);
            outp[n0 * 16 + jj] = r;
        }
    }
}

// ---------------------------------------------------------------------------
// SpMM1: g_hacc[dst] += g_A[src] * w   (16 threads/edge, ONE float4 RED each)
// ---------------------------------------------------------------------------
__global__ void spmm1_kernel(const float* __restrict__ ew,
                             const int* __restrict__ esrc,
                             const int* __restrict__ edst) {
    int gid = blockIdx.x * blockDim.x + threadIdx.x;
    int e = gid >> 4;
    if (e >= N_EDGES) return;
    int q = gid & 15;

    int s = __ldg(&esrc[e]);
    int d = __ldg(&edst[e]);
    float w = __ldg(&ew[e]);

    float4 a = ((const float4*)g_A)[s * 16 + q];
    float4 m = make_float4(a.x * w, a.y * w, a.z * w, a.w * w);
    atomicAdd((float4*)&g_hacc[d * NHID + q * 4], m);
}

// ---------------------------------------------------------------------------
// Layer2: h = relu(g_hacc + b1); g_B = h @ W2  (f32x2; 2 threads/node)
// ---------------------------------------------------------------------------
__global__ __launch_bounds__(256) void layer2_kernel(const float* __restrict__ b1,
                                                     const float* __restrict__ W2) {
    __shared__ float W2s[NHID * NCLASS]; // 10 KB
    __shared__ float b1s[NHID];

    for (int i = threadIdx.x; i < NHID * NCLASS; i += 256) W2s[i] = W2[i];
    if (threadIdx.x < NHID) b1s[threadIdx.x] = b1[threadIdx.x];
    __syncthreads();

    int tid = blockIdx.x * 256 + threadIdx.x;
    int node = tid >> 1;
    int half = tid & 1;
    if (node >= N_NODES) return;
    int cbase = half * 20;

    ull acc[10];
#pragma unroll
    for (int j = 0; j < 10; j++) acc[j] = 0ull;

    const float4* hin = (const float4*)(g_hacc + node * NHID);
#pragma unroll 4
    for (int k4 = 0; k4 < 16; k4++) {
        float4 hv = hin[k4];
        float hs[4] = {hv.x, hv.y, hv.z, hv.w};
#pragma unroll
        for (int u = 0; u < 4; u++) {
            int k = k4 * 4 + u;
            float h = fmaxf(hs[u] + b1s[k], 0.f);
            ull hh = pack2(h);
            const float4* wrow = (const float4*)(W2s + k * NCLASS + cbase);
#pragma unroll
            for (int jj = 0; jj < 5; jj++) {
                F4U2 w; w.f4 = wrow[jj];
                ffma2(acc[2 * jj],     hh, w.u2[0]);
                ffma2(acc[2 * jj + 1], hh, w.u2[1]);
            }
        }
    }

    float4* out = (float4*)(g_B + node * NCLASS + cbase);
#pragma unroll
    for (int jj = 0; jj < 5; jj++) {
        F4U2 o; o.u2[0] = acc[2 * jj]; o.u2[1] = acc[2 * jj + 1];
        out[jj] = o.f4;
    }
}

// ---------------------------------------------------------------------------
// SpMM2: g_lacc[dst] += g_B[src] * w   (10 threads/edge, ONE float4 RED each)
// ---------------------------------------------------------------------------
__global__ void spmm2_kernel(const float* __restrict__ ew,
                             const int* __restrict__ esrc,
                             const int* __restrict__ edst) {
    int gid = blockIdx.x * blockDim.x + threadIdx.x;
    int e = gid / 10;
    if (e >= N_EDGES) return;
    int q = gid - e * 10;

    int s = __ldg(&esrc[e]);
    int d = __ldg(&edst[e]);
    float w = __ldg(&ew[e]);

    float4 a = ((const float4*)g_B)[s * 10 + q];
    float4 m = make_float4(a.x * w, a.y * w, a.z * w, a.w * w);
    atomicAdd((float4*)&g_lacc[d * NCLASS + q * 4], m);
}

// ---------------------------------------------------------------------------
// Finalize: logits = g_lacc + b2; out[0:2M]=logits, out[2M:4M]=log_softmax
// ---------------------------------------------------------------------------
__global__ __launch_bounds__(128) void finalize_kernel(const float* __restrict__ b2,
                                                       float* __restrict__ out) {
    __shared__ float b2s[NCLASS];
    if (threadIdx.x < NCLASS) b2s[threadIdx.x] = b2[threadIdx.x];
    __syncthreads();

    int node = blockIdx.x * 128 + threadIdx.x;
    if (node >= N_NODES) return;

    float v[NCLASS];
    float mx = -INFINITY;
    const float4* lin = (const float4*)(g_lacc + node * NCLASS);
#pragma unroll
    for (int jj = 0; jj < 10; jj++) {
        float4 a = lin[jj];
        v[jj * 4 + 0] = a.x + b2s[jj * 4 + 0];
        v[jj * 4 + 1] = a.y + b2s[jj * 4 + 1];
        v[jj * 4 + 2] = a.z + b2s[jj * 4 + 2];
        v[jj * 4 + 3] = a.w + b2s[jj * 4 + 3];
    }
#pragma unroll
    for (int j = 0; j < NCLASS; j++) mx = fmaxf(mx, v[j]);
    float s = 0.f;
#pragma unroll
    for (int j = 0; j < NCLASS; j++) s += expf(v[j] - mx);
    float lse = mx + logf(s);

    float4* o1 = (float4*)(out + node * NCLASS);
    float4* o2 = (float4*)(out + LOGSM_OFF + node * NCLASS);
#pragma unroll
    for (int jj = 0; jj < 10; jj++) {
        float4 a = make_float4(v[jj * 4 + 0], v[jj * 4 + 1],
                               v[jj * 4 + 2], v[jj * 4 + 3]);
        o1[jj] = a;
        float4 b = make_float4(a.x - lse, a.y - lse, a.z - lse, a.w - lse);
        o2[jj] = b;
    }
}

// ---------------------------------------------------------------------------
extern "C" void kernel_launch(void* const* d_in, const int* in_sizes, int n_in,
                              void* d_out, int out_size) {
    const float* x   = (const float*)d_in[0];
    const float* W1  = (const float*)d_in[1];
    const float* b1  = (const float*)d_in[2];
    const float* W2  = (const float*)d_in[3];
    const float* b2  = (const float*)d_in[4];
    const float* ew  = (const float*)d_in[5];
    const int*  esrc = (const int*)d_in[6];
    const int*  edst = (const int*)d_in[7];
    float* out = (float*)d_out;

    // Allow 64KB dynamic smem for gemm1 (idempotent; no allocation involved)
    cudaFuncSetAttribute(gemm1_kernel,
                         cudaFuncAttributeMaxDynamicSharedMemorySize, 65536);

    // Zero accumulators
    {
        int n4 = (N_NODES * NHID) / 4;
        zero_acc_kernel<<<(n4 + 255) / 256, 256>>>();
    }
    // GEMM1 (K-split x2, 128 nodes/block, 64KB dynamic smem)
    gemm1_kernel<<<(N_NODES + 127) / 128, 256, 65536>>>(x, W1);
    // SpMM1 (vector RED scatter)
    {
        int total = N_EDGES * 16; // 12.8M
        spmm1_kernel<<<(total + 255) / 256, 256>>>(ew, esrc, edst);
    }
    // ReLU + bias + GEMM2 (2 threads/node)
    {
        int total = N_NODES * 2;
        layer2_kernel<<<(total + 255) / 256, 256>>>(b1, W2);
    }
    // SpMM2 (vector RED scatter)
    {
        int total = N_EDGES * 10; // 8M
        spmm2_kernel<<<(total + 255) / 256, 256>>>(ew, esrc, edst);
    }
    // bias + log_softmax + write both outputs
    finalize_kernel<<<(N_NODES + 127) / 128, 128>>>(b2, out);
}

// round 9
// speedup vs baseline: 1.5069x; 1.2559x over previous
#include <cuda_runtime.h>
#include <math.h>
#include <stdint.h>

#define N_NODES 50000
#define N_EDGES 800000
#define NFEAT   256
#define NHID    64
#define NCLASS  40
#define LOGSM_OFF (N_NODES * NCLASS)

typedef unsigned long long ull;

// Scratch (static __device__ — no allocations allowed)
__device__ float g_A[N_NODES * NHID];      // x @ W1
__device__ float g_hacc[N_NODES * NHID];   // spmm1 accumulator
__device__ float g_B[N_NODES * NCLASS];    // relu(hacc+b1) @ W2
__device__ float g_lacc[N_NODES * NCLASS]; // spmm2 accumulator

// ---------------------------------------------------------------------------
// f32x2 packed-FMA helpers (layer2)
// ---------------------------------------------------------------------------
__device__ __forceinline__ void ffma2(ull& acc, ull ab, ull w) {
    asm("fma.rn.f32x2 %0, %1, %2, %0;" : "+l"(acc) : "l"(ab), "l"(w));
}
__device__ __forceinline__ ull pack2(float v) {
    ull r;
    asm("mov.b64 %0, {%1, %1};" : "=l"(r) : "r"(__float_as_uint(v)));
    return r;
}
union F4U2 { float4 f4; ull u2[2]; };

// ---------------------------------------------------------------------------
// tf32 helpers
// ---------------------------------------------------------------------------
__device__ __forceinline__ uint32_t f2tf32(float f) {
    uint32_t r;
    asm("cvt.rna.tf32.f32 %0, %1;" : "=r"(r) : "f"(f));
    return r;
}
__device__ __forceinline__ void mma_tf32(float* d, const uint32_t* a,
                                         uint32_t b0, uint32_t b1) {
    asm volatile(
        "mma.sync.aligned.m16n8k8.row.col.f32.tf32.tf32.f32 "
        "{%0,%1,%2,%3}, {%4,%5,%6,%7}, {%8,%9}, {%0,%1,%2,%3};"
        : "+f"(d[0]), "+f"(d[1]), "+f"(d[2]), "+f"(d[3])
        : "r"(a[0]), "r"(a[1]), "r"(a[2]), "r"(a[3]), "r"(b0), "r"(b1));
}

// W1 smem tile: one K-half [128 k x 64 n] as float2(hi,lo), n-major.
// Stride KP=132 float2 => 2*KP = 264 ≡ 8 (mod 32): B-fragment banks
// (8n + 2k) mod 32 are distinct within each half-warp phase (n<4, k<4).
#define KP 132
#define G1_SMEM (64 * KP * 8)  // 67584 bytes

// ---------------------------------------------------------------------------
// Zero both accumulators
// ---------------------------------------------------------------------------
__global__ void zero_acc_kernel() {
    int i = blockIdx.x * blockDim.x + threadIdx.x;
    float4 z = make_float4(0.f, 0.f, 0.f, 0.f);
    if (i < (N_NODES * NHID) / 4)   ((float4*)g_hacc)[i] = z;
    if (i < (N_NODES * NCLASS) / 4) ((float4*)g_lacc)[i] = z;
}

// ---------------------------------------------------------------------------
// GEMM1 via mma.sync tf32 split-precision: g_A = x @ W1.
// Block 256 thr = 8 warps; warp w computes nodes [blk*128 + w*16, +16) x all
// 64 cols. K processed in 2 halves of 128; W1 half staged in smem as (hi,lo).
// 3 mma passes per (ntile, kstep): hi*hi + hi*lo + lo*hi (fp32 accumulate).
// ---------------------------------------------------------------------------
__global__ __launch_bounds__(256) void gemm1_tc_kernel(const float* __restrict__ x,
                                                       const float* __restrict__ W1) {
    extern __shared__ __align__(16) float2 Wt[]; // [64][KP]

    int tid = threadIdx.x;
    int warp = tid >> 5, lane = tid & 31;
    int grp = lane >> 2;      // groupID: node row / B col
    int tig = lane & 3;       // thread-in-group: k index

    int node0 = blockIdx.x * 128 + warp * 16;
    int r0 = node0 + grp;
    int r1 = r0 + 8;
    int rr0 = (r0 < N_NODES) ? r0 : (N_NODES - 1);
    int rr1 = (r1 < N_NODES) ? r1 : (N_NODES - 1);

    float d[8][4];
#pragma unroll
    for (int nt = 0; nt < 8; nt++)
#pragma unroll
        for (int j = 0; j < 4; j++) d[nt][j] = 0.f;

    for (int h = 0; h < 2; h++) {
        __syncthreads(); // previous half fully consumed
        // Stage W1 K-half [h*128, h*128+128) as (hi, lo) tf32 pairs, n-major
        for (int i = tid; i < 128 * 64; i += 256) {
            int kl = i >> 6;       // local k 0..127
            int n  = i & 63;
            float w = W1[(h * 128 + kl) * NHID + n];
            float hi = __uint_as_float(f2tf32(w));
            float lo = __uint_as_float(f2tf32(w - hi));
            Wt[n * KP + kl] = make_float2(hi, lo);
        }
        __syncthreads();

        int kg0 = h * 128;
#pragma unroll 4
        for (int ks = 0; ks < 16; ks++) {
            int kc = kg0 + ks * 8 + tig;
            // A fragment: rows {grp, grp+8}, cols {kc, kc+4}
            float a0 = __ldg(&x[rr0 * NFEAT + kc]);
            float a1 = __ldg(&x[rr1 * NFEAT + kc]);
            float a2 = __ldg(&x[rr0 * NFEAT + kc + 4]);
            float a3 = __ldg(&x[rr1 * NFEAT + kc + 4]);
            uint32_t ah[4], al[4];
            ah[0] = f2tf32(a0); al[0] = f2tf32(a0 - __uint_as_float(ah[0]));
            ah[1] = f2tf32(a1); al[1] = f2tf32(a1 - __uint_as_float(ah[1]));
            ah[2] = f2tf32(a2); al[2] = f2tf32(a2 - __uint_as_float(ah[2]));
            ah[3] = f2tf32(a3); al[3] = f2tf32(a3 - __uint_as_float(ah[3]));

            int kb = ks * 8 + tig;
#pragma unroll
            for (int nt = 0; nt < 8; nt++) {
                float2 p0 = Wt[(nt * 8 + grp) * KP + kb];       // k = tig
                float2 p1 = Wt[(nt * 8 + grp) * KP + kb + 4];   // k = tig+4
                uint32_t b0h = __float_as_uint(p0.x), b0l = __float_as_uint(p0.y);
                uint32_t b1h = __float_as_uint(p1.x), b1l = __float_as_uint(p1.y);
                mma_tf32(d[nt], ah, b0h, b1h);
                mma_tf32(d[nt], ah, b0l, b1l);
                mma_tf32(d[nt], al, b0h, b1h);
            }
        }
    }

    // Store D: thread owns cols {2*tig, 2*tig+1} per ntile, rows r0 and r1.
#pragma unroll
    for (int nt = 0; nt < 8; nt++) {
        int c = nt * 8 + 2 * tig;
        if (r0 < N_NODES)
            *(float2*)(g_A + r0 * NHID + c) = make_float2(d[nt][0], d[nt][1]);
        if (r1 < N_NODES)
            *(float2*)(g_A + r1 * NHID + c) = make_float2(d[nt][2], d[nt][3]);
    }
}

// ---------------------------------------------------------------------------
// SpMM1: g_hacc[dst] += g_A[src] * w   (16 threads/edge, ONE float4 RED each)
// ---------------------------------------------------------------------------
__global__ void spmm1_kernel(const float* __restrict__ ew,
                             const int* __restrict__ esrc,
                             const int* __restrict__ edst) {
    int gid = blockIdx.x * blockDim.x + threadIdx.x;
    int e = gid >> 4;
    if (e >= N_EDGES) return;
    int q = gid & 15;

    int s = __ldg(&esrc[e]);
    int d = __ldg(&edst[e]);
    float w = __ldg(&ew[e]);

    float4 a = ((const float4*)g_A)[s * 16 + q];
    float4 m = make_float4(a.x * w, a.y * w, a.z * w, a.w * w);
    atomicAdd((float4*)&g_hacc[d * NHID + q * 4], m);
}

// ---------------------------------------------------------------------------
// Layer2: h = relu(g_hacc + b1); g_B = h @ W2  (f32x2; 2 threads/node)
// ---------------------------------------------------------------------------
__global__ __launch_bounds__(256) void layer2_kernel(const float* __restrict__ b1,
                                                     const float* __restrict__ W2) {
    __shared__ float W2s[NHID * NCLASS]; // 10 KB
    __shared__ float b1s[NHID];

    for (int i = threadIdx.x; i < NHID * NCLASS; i += 256) W2s[i] = W2[i];
    if (threadIdx.x < NHID) b1s[threadIdx.x] = b1[threadIdx.x];
    __syncthreads();

    int tid = blockIdx.x * 256 + threadIdx.x;
    int node = tid >> 1;
    int half = tid & 1;
    if (node >= N_NODES) return;
    int cbase = half * 20;

    ull acc[10];
#pragma unroll
    for (int j = 0; j < 10; j++) acc[j] = 0ull;

    const float4* hin = (const float4*)(g_hacc + node * NHID);
#pragma unroll 4
    for (int k4 = 0; k4 < 16; k4++) {
        float4 hv = hin[k4];
        float hs[4] = {hv.x, hv.y, hv.z, hv.w};
#pragma unroll
        for (int u = 0; u < 4; u++) {
            int k = k4 * 4 + u;
            float h = fmaxf(hs[u] + b1s[k], 0.f);
            ull hh = pack2(h);
            const float4* wrow = (const float4*)(W2s + k * NCLASS + cbase);
#pragma unroll
            for (int jj = 0; jj < 5; jj++) {
                F4U2 w; w.f4 = wrow[jj];
                ffma2(acc[2 * jj],     hh, w.u2[0]);
                ffma2(acc[2 * jj + 1], hh, w.u2[1]);
            }
        }
    }

    float4* out = (float4*)(g_B + node * NCLASS + cbase);
#pragma unroll
    for (int jj = 0; jj < 5; jj++) {
        F4U2 o; o.u2[0] = acc[2 * jj]; o.u2[1] = acc[2 * jj + 1];
        out[jj] = o.f4;
    }
}

// ---------------------------------------------------------------------------
// SpMM2: g_lacc[dst] += g_B[src] * w   (10 threads/edge, ONE float4 RED each)
// ---------------------------------------------------------------------------
__global__ void spmm2_kernel(const float* __restrict__ ew,
                             const int* __restrict__ esrc,
                             const int* __restrict__ edst) {
    int gid = blockIdx.x * blockDim.x + threadIdx.x;
    int e = gid / 10;
    if (e >= N_EDGES) return;
    int q = gid - e * 10;

    int s = __ldg(&esrc[e]);
    int d = __ldg(&edst[e]);
    float w = __ldg(&ew[e]);

    float4 a = ((const float4*)g_B)[s * 10 + q];
    float4 m = make_float4(a.x * w, a.y * w, a.z * w, a.w * w);
    atomicAdd((float4*)&g_lacc[d * NCLASS + q * 4], m);
}

// ---------------------------------------------------------------------------
// Finalize: logits = g_lacc + b2; out[0:2M]=logits, out[2M:4M]=log_softmax
// ---------------------------------------------------------------------------
__global__ __launch_bounds__(128) void finalize_kernel(const float* __restrict__ b2,
                                                       float* __restrict__ out) {
    __shared__ float b2s[NCLASS];
    if (threadIdx.x < NCLASS) b2s[threadIdx.x] = b2[threadIdx.x];
    __syncthreads();

    int node = blockIdx.x * 128 + threadIdx.x;
    if (node >= N_NODES) return;

    float v[NCLASS];
    float mx = -INFINITY;
    const float4* lin = (const float4*)(g_lacc + node * NCLASS);
#pragma unroll
    for (int jj = 0; jj < 10; jj++) {
        float4 a = lin[jj];
        v[jj * 4 + 0] = a.x + b2s[jj * 4 + 0];
        v[jj * 4 + 1] = a.y + b2s[jj * 4 + 1];
        v[jj * 4 + 2] = a.z + b2s[jj * 4 + 2];
        v[jj * 4 + 3] = a.w + b2s[jj * 4 + 3];
    }
#pragma unroll
    for (int j = 0; j < NCLASS; j++) mx = fmaxf(mx, v[j]);
    float s = 0.f;
#pragma unroll
    for (int j = 0; j < NCLASS; j++) s += expf(v[j] - mx);
    float lse = mx + logf(s);

    float4* o1 = (float4*)(out + node * NCLASS);
    float4* o2 = (float4*)(out + LOGSM_OFF + node * NCLASS);
#pragma unroll
    for (int jj = 0; jj < 10; jj++) {
        float4 a = make_float4(v[jj * 4 + 0], v[jj * 4 + 1],
                               v[jj * 4 + 2], v[jj * 4 + 3]);
        o1[jj] = a;
        float4 b = make_float4(a.x - lse, a.y - lse, a.z - lse, a.w - lse);
        o2[jj] = b;
    }
}

// ---------------------------------------------------------------------------
extern "C" void kernel_launch(void* const* d_in, const int* in_sizes, int n_in,
                              void* d_out, int out_size) {
    const float* x   = (const float*)d_in[0];
    const float* W1  = (const float*)d_in[1];
    const float* b1  = (const float*)d_in[2];
    const float* W2  = (const float*)d_in[3];
    const float* b2  = (const float*)d_in[4];
    const float* ew  = (const float*)d_in[5];
    const int*  esrc = (const int*)d_in[6];
    const int*  edst = (const int*)d_in[7];
    float* out = (float*)d_out;

    cudaFuncSetAttribute(gemm1_tc_kernel,
                         cudaFuncAttributeMaxDynamicSharedMemorySize, G1_SMEM);

    // Zero accumulators
    {
        int n4 = (N_NODES * NHID) / 4;
        zero_acc_kernel<<<(n4 + 255) / 256, 256>>>();
    }
    // GEMM1 via tf32 mma.sync (128 nodes per block)
    {
        int nblk = (N_NODES + 127) / 128; // 391
        gemm1_tc_kernel<<<nblk, 256, G1_SMEM>>>(x, W1);
    }
    // SpMM1 (vector RED scatter)
    {
        int total = N_EDGES * 16; // 12.8M
        spmm1_kernel<<<(total + 255) / 256, 256>>>(ew, esrc, edst);
    }
    // ReLU + bias + GEMM2 (2 threads/node)
    {
        int total = N_NODES * 2;
        layer2_kernel<<<(total + 255) / 256, 256>>>(b1, W2);
    }
    // SpMM2 (vector RED scatter)
    {
        int total = N_EDGES * 10; // 8M
        spmm2_kernel<<<(total + 255) / 256, 256>>>(ew, esrc, edst);
    }
    // bias + log_softmax + write both outputs
    finalize_kernel<<<(N_NODES + 127) / 128, 128>>>(b2, out);
}

// round 10
// speedup vs baseline: 1.5931x; 1.0572x over previous
#include <cuda_runtime.h>
#include <math.h>
#include <stdint.h>

#define N_NODES 50000
#define N_EDGES 800000
#define NFEAT   256
#define NHID    64
#define NCLASS  40
#define LOGSM_OFF (N_NODES * NCLASS)

typedef unsigned long long ull;

// Scratch (static __device__ — no allocations allowed)
__device__ float g_A[N_NODES * NHID];      // x @ W1
__device__ float g_hacc[N_NODES * NHID];   // spmm1 accumulator
__device__ float g_B[N_NODES * NCLASS];    // relu(hacc+b1) @ W2
__device__ float g_lacc[N_NODES * NCLASS]; // spmm2 accumulator

// ---------------------------------------------------------------------------
// tf32 helpers
// ---------------------------------------------------------------------------
__device__ __forceinline__ uint32_t f2tf32(float f) {
    uint32_t r;
    asm("cvt.rna.tf32.f32 %0, %1;" : "=r"(r) : "f"(f));
    return r;
}
__device__ __forceinline__ void mma_tf32(float* d, const uint32_t* a,
                                         uint32_t b0, uint32_t b1) {
    asm volatile(
        "mma.sync.aligned.m16n8k8.row.col.f32.tf32.tf32.f32 "
        "{%0,%1,%2,%3}, {%4,%5,%6,%7}, {%8,%9}, {%0,%1,%2,%3};"
        : "+f"(d[0]), "+f"(d[1]), "+f"(d[2]), "+f"(d[3])
        : "r"(a[0]), "r"(a[1]), "r"(a[2]), "r"(a[3]), "r"(b0), "r"(b1));
}

// W1 smem tile: one K-half [128 k x 64 n] as float2(hi,lo), n-major.
// Stride KP=132 float2 => bank (8n + 2k) mod 32 conflict-free.
#define KP 132
#define G1_SMEM (64 * KP * 8)  // 67584 bytes

// ---------------------------------------------------------------------------
// GEMM1 via mma.sync tf32 split-precision: g_A = x @ W1.
// Also zeroes g_hacc / g_lacc in the prologue (replaces zero_acc_kernel).
// ---------------------------------------------------------------------------
__global__ __launch_bounds__(256) void gemm1_tc_kernel(const float* __restrict__ x,
                                                       const float* __restrict__ W1) {
    extern __shared__ __align__(16) float2 Wt[]; // [64][KP]

    // ---- fused accumulator zeroing (graph replays need this every call) ----
    {
        int idx = blockIdx.x * 256 + threadIdx.x;
        int nthr = gridDim.x * 256;
        float4 z = make_float4(0.f, 0.f, 0.f, 0.f);
        float4* h4 = (float4*)g_hacc;
        float4* l4 = (float4*)g_lacc;
        for (int i = idx; i < (N_NODES * NHID) / 4; i += nthr) h4[i] = z;
        for (int i = idx; i < (N_NODES * NCLASS) / 4; i += nthr) l4[i] = z;
    }

    int tid = threadIdx.x;
    int warp = tid >> 5, lane = tid & 31;
    int grp = lane >> 2;      // node row / B col group
    int tig = lane & 3;       // k index within group

    int node0 = blockIdx.x * 128 + warp * 16;
    int r0 = node0 + grp;
    int r1 = r0 + 8;
    int rr0 = (r0 < N_NODES) ? r0 : (N_NODES - 1);
    int rr1 = (r1 < N_NODES) ? r1 : (N_NODES - 1);

    float d[8][4];
#pragma unroll
    for (int nt = 0; nt < 8; nt++)
#pragma unroll
        for (int j = 0; j < 4; j++) d[nt][j] = 0.f;

    for (int h = 0; h < 2; h++) {
        __syncthreads();
        for (int i = tid; i < 128 * 64; i += 256) {
            int kl = i >> 6;
            int n  = i & 63;
            float w = W1[(h * 128 + kl) * NHID + n];
            float hi = __uint_as_float(f2tf32(w));
            float lo = __uint_as_float(f2tf32(w - hi));
            Wt[n * KP + kl] = make_float2(hi, lo);
        }
        __syncthreads();

        int kg0 = h * 128;
#pragma unroll 4
        for (int ks = 0; ks < 16; ks++) {
            int kc = kg0 + ks * 8 + tig;
            float a0 = __ldg(&x[rr0 * NFEAT + kc]);
            float a1 = __ldg(&x[rr1 * NFEAT + kc]);
            float a2 = __ldg(&x[rr0 * NFEAT + kc + 4]);
            float a3 = __ldg(&x[rr1 * NFEAT + kc + 4]);
            uint32_t ah[4], al[4];
            ah[0] = f2tf32(a0); al[0] = f2tf32(a0 - __uint_as_float(ah[0]));
            ah[1] = f2tf32(a1); al[1] = f2tf32(a1 - __uint_as_float(ah[1]));
            ah[2] = f2tf32(a2); al[2] = f2tf32(a2 - __uint_as_float(ah[2]));
            ah[3] = f2tf32(a3); al[3] = f2tf32(a3 - __uint_as_float(ah[3]));

            int kb = ks * 8 + tig;
#pragma unroll
            for (int nt = 0; nt < 8; nt++) {
                float2 p0 = Wt[(nt * 8 + grp) * KP + kb];
                float2 p1 = Wt[(nt * 8 + grp) * KP + kb + 4];
                uint32_t b0h = __float_as_uint(p0.x), b0l = __float_as_uint(p0.y);
                uint32_t b1h = __float_as_uint(p1.x), b1l = __float_as_uint(p1.y);
                mma_tf32(d[nt], ah, b0h, b1h);
                mma_tf32(d[nt], ah, b0l, b1l);
                mma_tf32(d[nt], al, b0h, b1h);
            }
        }
    }

#pragma unroll
    for (int nt = 0; nt < 8; nt++) {
        int c = nt * 8 + 2 * tig;
        if (r0 < N_NODES)
            *(float2*)(g_A + r0 * NHID + c) = make_float2(d[nt][0], d[nt][1]);
        if (r1 < N_NODES)
            *(float2*)(g_A + r1 * NHID + c) = make_float2(d[nt][2], d[nt][3]);
    }
}

// ---------------------------------------------------------------------------
// SpMM1: g_hacc[dst] += g_A[src] * w   (16 threads/edge, ONE float4 RED each)
// ---------------------------------------------------------------------------
__global__ void spmm1_kernel(const float* __restrict__ ew,
                             const int* __restrict__ esrc,
                             const int* __restrict__ edst) {
    int gid = blockIdx.x * blockDim.x + threadIdx.x;
    int e = gid >> 4;
    if (e >= N_EDGES) return;
    int q = gid & 15;

    int s = __ldg(&esrc[e]);
    int d = __ldg(&edst[e]);
    float w = __ldg(&ew[e]);

    float4 a = ((const float4*)g_A)[s * 16 + q];
    float4 m = make_float4(a.x * w, a.y * w, a.z * w, a.w * w);
    atomicAdd((float4*)&g_hacc[d * NHID + q * 4], m);
}

// ---------------------------------------------------------------------------
// Layer2 via mma.sync tf32: g_B = relu(g_hacc + b1) @ W2.
// Warp = 16 nodes x 40 cols; K=64; 5 n-tiles; split-precision 3-pass.
// W2 smem stride 68 float2 => bank (8n + 2k) mod 32 conflict-free.
// ---------------------------------------------------------------------------
#define KP2 68
__global__ __launch_bounds__(256) void layer2_tc_kernel(const float* __restrict__ b1,
                                                        const float* __restrict__ W2) {
    __shared__ float2 W2t[NCLASS * KP2]; // 40*68*8 = 21760 B
    __shared__ float b1s[NHID];

    int tid = threadIdx.x;
    // Stage W2 (hi,lo): W2 is [64 k][40 n] row-major
    for (int i = tid; i < NHID * NCLASS; i += 256) {
        int k = i / NCLASS, n = i - k * NCLASS;
        float w = W2[i];
        float hi = __uint_as_float(f2tf32(w));
        float lo = __uint_as_float(f2tf32(w - hi));
        W2t[n * KP2 + k] = make_float2(hi, lo);
    }
    if (tid < NHID) b1s[tid] = b1[tid];
    __syncthreads();

    int warp = tid >> 5, lane = tid & 31;
    int grp = lane >> 2, tig = lane & 3;

    int node0 = blockIdx.x * 128 + warp * 16;
    int r0 = node0 + grp;
    int r1 = r0 + 8;
    int rr0 = (r0 < N_NODES) ? r0 : (N_NODES - 1);
    int rr1 = (r1 < N_NODES) ? r1 : (N_NODES - 1);

    float d[5][4];
#pragma unroll
    for (int nt = 0; nt < 5; nt++)
#pragma unroll
        for (int j = 0; j < 4; j++) d[nt][j] = 0.f;

#pragma unroll
    for (int ks = 0; ks < 8; ks++) {
        int kc = ks * 8 + tig;
        float a0 = fmaxf(g_hacc[rr0 * NHID + kc]     + b1s[kc],     0.f);
        float a1 = fmaxf(g_hacc[rr1 * NHID + kc]     + b1s[kc],     0.f);
        float a2 = fmaxf(g_hacc[rr0 * NHID + kc + 4] + b1s[kc + 4], 0.f);
        float a3 = fmaxf(g_hacc[rr1 * NHID + kc + 4] + b1s[kc + 4], 0.f);
        uint32_t ah[4], al[4];
        ah[0] = f2tf32(a0); al[0] = f2tf32(a0 - __uint_as_float(ah[0]));
        ah[1] = f2tf32(a1); al[1] = f2tf32(a1 - __uint_as_float(ah[1]));
        ah[2] = f2tf32(a2); al[2] = f2tf32(a2 - __uint_as_float(ah[2]));
        ah[3] = f2tf32(a3); al[3] = f2tf32(a3 - __uint_as_float(ah[3]));

#pragma unroll
        for (int nt = 0; nt < 5; nt++) {
            float2 p0 = W2t[(nt * 8 + grp) * KP2 + kc];
            float2 p1 = W2t[(nt * 8 + grp) * KP2 + kc + 4];
            uint32_t b0h = __float_as_uint(p0.x), b0l = __float_as_uint(p0.y);
            uint32_t b1h = __float_as_uint(p1.x), b1l = __float_as_uint(p1.y);
            mma_tf32(d[nt], ah, b0h, b1h);
            mma_tf32(d[nt], ah, b0l, b1l);
            mma_tf32(d[nt], al, b0h, b1h);
        }
    }

#pragma unroll
    for (int nt = 0; nt < 5; nt++) {
        int c = nt * 8 + 2 * tig;
        if (r0 < N_NODES)
            *(float2*)(g_B + r0 * NCLASS + c) = make_float2(d[nt][0], d[nt][1]);
        if (r1 < N_NODES)
            *(float2*)(g_B + r1 * NCLASS + c) = make_float2(d[nt][2], d[nt][3]);
    }
}

// ---------------------------------------------------------------------------
// SpMM2: g_lacc[dst] += g_B[src] * w   (10 threads/edge, ONE float4 RED each)
// ---------------------------------------------------------------------------
__global__ void spmm2_kernel(const float* __restrict__ ew,
                             const int* __restrict__ esrc,
                             const int* __restrict__ edst) {
    int gid = blockIdx.x * blockDim.x + threadIdx.x;
    int e = gid / 10;
    if (e >= N_EDGES) return;
    int q = gid - e * 10;

    int s = __ldg(&esrc[e]);
    int d = __ldg(&edst[e]);
    float w = __ldg(&ew[e]);

    float4 a = ((const float4*)g_B)[s * 10 + q];
    float4 m = make_float4(a.x * w, a.y * w, a.z * w, a.w * w);
    atomicAdd((float4*)&g_lacc[d * NCLASS + q * 4], m);
}

// ---------------------------------------------------------------------------
// Finalize: logits = g_lacc + b2; out[0:2M]=logits, out[2M:4M]=log_softmax
// ---------------------------------------------------------------------------
__global__ __launch_bounds__(128) void finalize_kernel(const float* __restrict__ b2,
                                                       float* __restrict__ out) {
    __shared__ float b2s[NCLASS];
    if (threadIdx.x < NCLASS) b2s[threadIdx.x] = b2[threadIdx.x];
    __syncthreads();

    int node = blockIdx.x * 128 + threadIdx.x;
    if (node >= N_NODES) return;

    float v[NCLASS];
    float mx = -INFINITY;
    const float4* lin = (const float4*)(g_lacc + node * NCLASS);
#pragma unroll
    for (int jj = 0; jj < 10; jj++) {
        float4 a = lin[jj];
        v[jj * 4 + 0] = a.x + b2s[jj * 4 + 0];
        v[jj * 4 + 1] = a.y + b2s[jj * 4 + 1];
        v[jj * 4 + 2] = a.z + b2s[jj * 4 + 2];
        v[jj * 4 + 3] = a.w + b2s[jj * 4 + 3];
    }
#pragma unroll
    for (int j = 0; j < NCLASS; j++) mx = fmaxf(mx, v[j]);
    float s = 0.f;
#pragma unroll
    for (int j = 0; j < NCLASS; j++) s += expf(v[j] - mx);
    float lse = mx + logf(s);

    float4* o1 = (float4*)(out + node * NCLASS);
    float4* o2 = (float4*)(out + LOGSM_OFF + node * NCLASS);
#pragma unroll
    for (int jj = 0; jj < 10; jj++) {
        float4 a = make_float4(v[jj * 4 + 0], v[jj * 4 + 1],
                               v[jj * 4 + 2], v[jj * 4 + 3]);
        o1[jj] = a;
        float4 b = make_float4(a.x - lse, a.y - lse, a.z - lse, a.w - lse);
        o2[jj] = b;
    }
}

// ---------------------------------------------------------------------------
extern "C" void kernel_launch(void* const* d_in, const int* in_sizes, int n_in,
                              void* d_out, int out_size) {
    const float* x   = (const float*)d_in[0];
    const float* W1  = (const float*)d_in[1];
    const float* b1  = (const float*)d_in[2];
    const float* W2  = (const float*)d_in[3];
    const float* b2  = (const float*)d_in[4];
    const float* ew  = (const float*)d_in[5];
    const int*  esrc = (const int*)d_in[6];
    const int*  edst = (const int*)d_in[7];
    float* out = (float*)d_out;

    cudaFuncSetAttribute(gemm1_tc_kernel,
                         cudaFuncAttributeMaxDynamicSharedMemorySize, G1_SMEM);

    // GEMM1 via tf32 mma.sync + fused accumulator zeroing
    {
        int nblk = (N_NODES + 127) / 128; // 391
        gemm1_tc_kernel<<<nblk, 256, G1_SMEM>>>(x, W1);
    }
    // SpMM1 (vector RED scatter)
    {
        int total = N_EDGES * 16; // 12.8M
        spmm1_kernel<<<(total + 255) / 256, 256>>>(ew, esrc, edst);
    }
    // ReLU + bias + GEMM2 via tf32 mma.sync
    {
        int nblk = (N_NODES + 127) / 128; // 391
        layer2_tc_kernel<<<nblk, 256>>>(b1, W2);
    }
    // SpMM2 (vector RED scatter)
    {
        int total = N_EDGES * 10; // 8M
        spmm2_kernel<<<(total + 255) / 256, 256>>>(ew, esrc, edst);
    }
    // bias + log_softmax + write both outputs
    finalize_kernel<<<(N_NODES + 127) / 128, 128>>>(b2, out);
}